// round 1
// baseline (speedup 1.0000x reference)
#include <cuda_runtime.h>
#include <cuda_bf16.h>
#include <math.h>

// ---------------------------------------------------------------------------
// Problem constants
// ---------------------------------------------------------------------------
#define BATCH   32
#define HW      32          // H = W = 32
#define C_DIM   384
#define NHEADS  12
#define HEADD   32
#define WS      8
#define SS      4
#define NTOK    64          // tokens per window
#define NWIN    16          // windows per image
#define M_TOK   (BATCH * HW * HW)      // 32768 rows
#define QKV_N   (3 * C_DIM)            // 1152
#define HIDDEN  (4 * C_DIM)            // 1536
#define SCALE_ATTN 0.17677669529663687f   // 1/sqrt(32)

// ---------------------------------------------------------------------------
// Scratch buffers (device globals; no allocation allowed)
// ---------------------------------------------------------------------------
__device__ float g_xw  [(size_t)M_TOK * C_DIM];    // LN1+shift+partition output
__device__ float g_qkv [(size_t)M_TOK * QKV_N];    // qkv
__device__ float g_attn[(size_t)M_TOK * C_DIM];    // attention output (window layout)
__device__ float g_x1  [(size_t)M_TOK * C_DIM];    // x + attn branch (image layout)
__device__ float g_xn2 [(size_t)M_TOK * C_DIM];    // LN2 output
__device__ float g_h   [(size_t)M_TOK * HIDDEN];   // fc1+gelu output

// ---------------------------------------------------------------------------
// window<->image row mapping.
// Window row (w = b*16 + wh*4 + ww, n = r*8+cc) corresponds to image token
// b*1024 + ((wh*8+r+4)%32)*32 + ((ww*8+cc+4)%32)  (both for the shifted gather
// and the reverse+unshift scatter -- the same permutation).
// ---------------------------------------------------------------------------
__device__ __forceinline__ int win2img(int row) {
    int w  = row >> 6;
    int n  = row & 63;
    int b  = w >> 4;
    int wi = w & 15;
    int wh = wi >> 2, ww = wi & 3;
    int r  = n >> 3,  cc = n & 7;
    int i  = (wh * 8 + r + SS) & 31;
    int j  = (ww * 8 + cc + SS) & 31;
    return b * 1024 + i * 32 + j;
}

__device__ __forceinline__ float gelu_tanh(float x) {
    float x3 = x * x * x;
    return 0.5f * x * (1.0f + tanhf(0.7978845608028654f * (x + 0.044715f * x3)));
}

// ---------------------------------------------------------------------------
// LayerNorm kernel. One block (128 threads) per output row (384 channels).
// SHIFT=true : output row is window-layout, input row is the mapped image token.
// SHIFT=false: identity mapping.
// ---------------------------------------------------------------------------
template <bool SHIFT>
__global__ void ln_kernel(const float* __restrict__ x,
                          const float* __restrict__ gamma,
                          const float* __restrict__ beta,
                          float* __restrict__ out) {
    int row = blockIdx.x;
    int src = SHIFT ? win2img(row) : row;
    const float* xp = x + (size_t)src * C_DIM;
    int tid = threadIdx.x;

    float v0 = xp[tid];
    float v1 = xp[tid + 128];
    float v2 = xp[tid + 256];
    float s  = v0 + v1 + v2;
    float sq = v0 * v0 + v1 * v1 + v2 * v2;

    // block reduce (4 warps)
    #pragma unroll
    for (int o = 16; o > 0; o >>= 1) {
        s  += __shfl_down_sync(0xffffffffu, s,  o);
        sq += __shfl_down_sync(0xffffffffu, sq, o);
    }
    __shared__ float sa[4], sb[4];
    int wp = tid >> 5, ln = tid & 31;
    if (ln == 0) { sa[wp] = s; sb[wp] = sq; }
    __syncthreads();
    s  = sa[0] + sa[1] + sa[2] + sa[3];
    sq = sb[0] + sb[1] + sb[2] + sb[3];

    float mean = s * (1.0f / C_DIM);
    float var  = sq * (1.0f / C_DIM) - mean * mean;
    float inv  = rsqrtf(var + 1e-5f);

    float* op = out + (size_t)row * C_DIM;
    op[tid]       = (v0 - mean) * inv * gamma[tid]       + beta[tid];
    op[tid + 128] = (v1 - mean) * inv * gamma[tid + 128] + beta[tid + 128];
    op[tid + 256] = (v2 - mean) * inv * gamma[tid + 256] + beta[tid + 256];
}

// ---------------------------------------------------------------------------
// Tiled SGEMM: C = A[M,K] @ B[K,N] (+ bias, + epilogue).
// BM=BN=128, BK=16, 256 threads, 8x8 micro-tile per thread.
// All problem dims divide the tile sizes (M=32768; N in {384,1152,1536};
// K in {384,1536}) -> no bounds checks.
// EPI: 0 = bias                        (qkv)
//      1 = bias + gelu                 (fc1)
//      2 = bias + res[row]             (fc2 + residual)
//      3 = bias + res[dst], write dst  (proj + window-reverse scatter + residual)
// ---------------------------------------------------------------------------
template <int EPI>
__global__ __launch_bounds__(256)
void gemm128(const float* __restrict__ A, const float* __restrict__ B,
             const float* __restrict__ bias, const float* __restrict__ res,
             float* __restrict__ Cmat, int M, int N, int K) {
    __shared__ float As[16][132];   // padded: transposed A tile
    __shared__ float Bs[16][128];

    int tid = threadIdx.x;
    int bm  = blockIdx.y * 128;
    int bn  = blockIdx.x * 128;
    int ty  = tid >> 4;     // 0..15
    int tx  = tid & 15;     // 0..15

    const float* Aptr = A + (size_t)bm * K;
    const float* Bptr = B + bn;

    float acc[8][8];
    #pragma unroll
    for (int i = 0; i < 8; i++)
        #pragma unroll
        for (int j = 0; j < 8; j++) acc[i][j] = 0.0f;

    for (int k0 = 0; k0 < K; k0 += 16) {
        // load A tile 128x16 (512 float4, 2 per thread), store transposed
        #pragma unroll
        for (int it = 0; it < 2; it++) {
            int f  = tid + it * 256;
            int r  = f >> 2;
            int c4 = (f & 3) * 4;
            float4 av = *(const float4*)&Aptr[(size_t)r * K + k0 + c4];
            As[c4 + 0][r] = av.x;
            As[c4 + 1][r] = av.y;
            As[c4 + 2][r] = av.z;
            As[c4 + 3][r] = av.w;
        }
        // load B tile 16x128 (512 float4, 2 per thread)
        #pragma unroll
        for (int it = 0; it < 2; it++) {
            int f  = tid + it * 256;
            int r  = f >> 5;
            int c4 = (f & 31) * 4;
            *(float4*)&Bs[r][c4] = *(const float4*)&Bptr[(size_t)(k0 + r) * N + c4];
        }
        __syncthreads();

        #pragma unroll
        for (int k = 0; k < 16; k++) {
            float a[8], b[8];
            *(float4*)&a[0] = *(const float4*)&As[k][ty * 8];
            *(float4*)&a[4] = *(const float4*)&As[k][ty * 8 + 4];
            *(float4*)&b[0] = *(const float4*)&Bs[k][tx * 8];
            *(float4*)&b[4] = *(const float4*)&Bs[k][tx * 8 + 4];
            #pragma unroll
            for (int i = 0; i < 8; i++)
                #pragma unroll
                for (int j = 0; j < 8; j++)
                    acc[i][j] = fmaf(a[i], b[j], acc[i][j]);
        }
        __syncthreads();
    }

    // epilogue
    int col0 = bn + tx * 8;
    float bv[8];
    #pragma unroll
    for (int j = 0; j < 8; j++) bv[j] = bias[col0 + j];

    #pragma unroll
    for (int i = 0; i < 8; i++) {
        int row  = bm + ty * 8 + i;
        int orow = (EPI == 3) ? win2img(row) : row;
        float v[8];
        #pragma unroll
        for (int j = 0; j < 8; j++) {
            float t = acc[i][j] + bv[j];
            if (EPI == 1) t = gelu_tanh(t);
            if (EPI == 2 || EPI == 3) t += res[(size_t)orow * N + col0 + j];
            v[j] = t;
        }
        float* cp = Cmat + (size_t)orow * N + col0;
        *(float4*)&cp[0] = *(const float4*)&v[0];
        *(float4*)&cp[4] = *(const float4*)&v[4];
    }
}

// ---------------------------------------------------------------------------
// Windowed attention. One block per (window, head): 512*12 = 6144 blocks,
// 128 threads. q,k,v tiles are 64x32. Relative-position bias and the
// shift mask are computed analytically (no precomputed index tables).
// ---------------------------------------------------------------------------
__global__ __launch_bounds__(128)
void attn_kernel(const float* __restrict__ qkv,
                 const float* __restrict__ table,   // [(2*8-1)^2=225, 12]
                 float* __restrict__ out) {
    __shared__ float qs[64][33];
    __shared__ float ks[64][33];
    __shared__ float vs[64][32];      // unpadded: read d-contiguous only
    __shared__ float S[64][64];
    __shared__ int   cnt[64];

    int blk = blockIdx.x;
    int w   = blk / NHEADS;
    int h   = blk - w * NHEADS;
    int tid = threadIdx.x;

    const float* base = qkv + (size_t)w * NTOK * QKV_N + h * HEADD;
    for (int f = tid; f < 512; f += 128) {
        int n = f >> 3;
        int d = (f & 7) * 4;
        float4 qv = *(const float4*)&base[(size_t)n * QKV_N + d];
        float4 kv = *(const float4*)&base[(size_t)n * QKV_N + C_DIM + d];
        float4 vv = *(const float4*)&base[(size_t)n * QKV_N + 2 * C_DIM + d];
        qs[n][d + 0] = qv.x * SCALE_ATTN;
        qs[n][d + 1] = qv.y * SCALE_ATTN;
        qs[n][d + 2] = qv.z * SCALE_ATTN;
        qs[n][d + 3] = qv.w * SCALE_ATTN;
        ks[n][d + 0] = kv.x; ks[n][d + 1] = kv.y;
        ks[n][d + 2] = kv.z; ks[n][d + 3] = kv.w;
        *(float4*)&vs[n][d] = vv;
    }
    if (tid < 64) {
        int wi = w & 15;
        int wh = wi >> 2, ww = wi & 3;
        int i = wh * 8 + (tid >> 3);
        int j = ww * 8 + (tid & 7);
        int ri = (i < 24) ? 0 : ((i < 28) ? 1 : 2);
        int rj = (j < 24) ? 0 : ((j < 28) ? 1 : 2);
        cnt[tid] = ri * 3 + rj;
    }
    __syncthreads();

    // S = q * k^T  (+ rel-pos bias + shift mask). Each thread: 8 (n, m0..m0+3) groups.
    for (int e = tid; e < 1024; e += 128) {
        int n  = e >> 4;
        int m0 = (e & 15) * 4;
        float s0 = 0.f, s1 = 0.f, s2 = 0.f, s3 = 0.f;
        #pragma unroll
        for (int d = 0; d < 32; d++) {
            float q = qs[n][d];
            s0 = fmaf(q, ks[m0 + 0][d], s0);
            s1 = fmaf(q, ks[m0 + 1][d], s1);
            s2 = fmaf(q, ks[m0 + 2][d], s2);
            s3 = fmaf(q, ks[m0 + 3][d], s3);
        }
        int r1 = n >> 3, c1 = n & 7;
        int cn = cnt[n];
        #pragma unroll
        for (int u = 0; u < 4; u++) {
            int m  = m0 + u;
            int r2 = m >> 3, c2 = m & 7;
            int rel = (r1 - r2 + 7) * 15 + (c1 - c2 + 7);
            float s = (u == 0 ? s0 : u == 1 ? s1 : u == 2 ? s2 : s3);
            s += __ldg(&table[rel * NHEADS + h]);
            if (cn != cnt[m]) s -= 100.0f;
            S[n][m] = s;
        }
    }
    __syncthreads();

    // softmax: one warp handles a row at a time (2 elems per lane)
    int wp = tid >> 5, ln = tid & 31;
    for (int r = wp; r < 64; r += 4) {
        float a0 = S[r][ln], a1 = S[r][ln + 32];
        float mx = fmaxf(a0, a1);
        #pragma unroll
        for (int o = 16; o > 0; o >>= 1) mx = fmaxf(mx, __shfl_xor_sync(0xffffffffu, mx, o));
        a0 = __expf(a0 - mx);
        a1 = __expf(a1 - mx);
        float sm = a0 + a1;
        #pragma unroll
        for (int o = 16; o > 0; o >>= 1) sm += __shfl_xor_sync(0xffffffffu, sm, o);
        float inv = 1.0f / sm;
        S[r][ln]      = a0 * inv;
        S[r][ln + 32] = a1 * inv;
    }
    __syncthreads();

    // out = S @ V, written to [token, h*32 + d] (the 'wnhd' layout)
    float* obase = out + (size_t)w * NTOK * C_DIM + h * HEADD;
    for (int e = tid; e < 512; e += 128) {
        int n  = e >> 3;
        int d0 = (e & 7) * 4;
        float sx = 0.f, sy = 0.f, sz = 0.f, sw = 0.f;
        #pragma unroll
        for (int m = 0; m < 64; m++) {
            float p = S[n][m];
            float4 vv = *(const float4*)&vs[m][d0];
            sx = fmaf(p, vv.x, sx);
            sy = fmaf(p, vv.y, sy);
            sz = fmaf(p, vv.z, sz);
            sw = fmaf(p, vv.w, sw);
        }
        float4 o4 = make_float4(sx, sy, sz, sw);
        *(float4*)&obase[(size_t)n * C_DIM + d0] = o4;
    }
}

// ---------------------------------------------------------------------------
// launch
// ---------------------------------------------------------------------------
extern "C" void kernel_launch(void* const* d_in, const int* in_sizes, int n_in,
                              void* d_out, int out_size) {
    const float* x       = (const float*)d_in[0];
    const float* n1g     = (const float*)d_in[1];
    const float* n1b     = (const float*)d_in[2];
    const float* qkv_w   = (const float*)d_in[3];
    const float* qkv_b   = (const float*)d_in[4];
    const float* table   = (const float*)d_in[5];
    const float* proj_w  = (const float*)d_in[6];
    const float* proj_b  = (const float*)d_in[7];
    const float* n2g     = (const float*)d_in[8];
    const float* n2b     = (const float*)d_in[9];
    const float* fc1_w   = (const float*)d_in[10];
    const float* fc1_b   = (const float*)d_in[11];
    const float* fc2_w   = (const float*)d_in[12];
    const float* fc2_b   = (const float*)d_in[13];
    float* out = (float*)d_out;

    static float *p_xw = nullptr, *p_qkv = nullptr, *p_attn = nullptr,
                 *p_x1 = nullptr, *p_xn2 = nullptr, *p_h = nullptr;
    if (!p_xw) {
        cudaGetSymbolAddress((void**)&p_xw,   g_xw);
        cudaGetSymbolAddress((void**)&p_qkv,  g_qkv);
        cudaGetSymbolAddress((void**)&p_attn, g_attn);
        cudaGetSymbolAddress((void**)&p_x1,   g_x1);
        cudaGetSymbolAddress((void**)&p_xn2,  g_xn2);
        cudaGetSymbolAddress((void**)&p_h,    g_h);
    }

    // 1) LN1 + shift + window partition
    ln_kernel<true><<<M_TOK, 128>>>(x, n1g, n1b, p_xw);

    // 2) QKV = xw @ qkv_w + qkv_b      [32768 x 1152], K=384
    {
        dim3 grid(QKV_N / 128, M_TOK / 128);
        gemm128<0><<<grid, 256>>>(p_xw, qkv_w, qkv_b, nullptr, p_qkv,
                                  M_TOK, QKV_N, C_DIM);
    }

    // 3) windowed attention
    attn_kernel<<<512 * NHEADS, 128>>>(p_qkv, table, p_attn);

    // 4) proj + window-reverse/unshift scatter + residual -> x1 (image layout)
    {
        dim3 grid(C_DIM / 128, M_TOK / 128);
        gemm128<3><<<grid, 256>>>(p_attn, proj_w, proj_b, x, p_x1,
                                  M_TOK, C_DIM, C_DIM);
    }

    // 5) LN2
    ln_kernel<false><<<M_TOK, 128>>>(p_x1, n2g, n2b, p_xn2);

    // 6) FC1 + GELU -> h   [32768 x 1536], K=384
    {
        dim3 grid(HIDDEN / 128, M_TOK / 128);
        gemm128<1><<<grid, 256>>>(p_xn2, fc1_w, fc1_b, nullptr, p_h,
                                  M_TOK, HIDDEN, C_DIM);
    }

    // 7) FC2 + residual -> out   [32768 x 384], K=1536
    {
        dim3 grid(C_DIM / 128, M_TOK / 128);
        gemm128<2><<<grid, 256>>>(p_h, fc2_w, fc2_b, p_x1, out,
                                  M_TOK, C_DIM, HIDDEN);
    }
}

// round 7
// speedup vs baseline: 1.9865x; 1.9865x over previous
#include <cuda_runtime.h>
#include <cuda_bf16.h>
#include <math.h>
#include <stdint.h>

// ---------------------------------------------------------------------------
// Problem constants
// ---------------------------------------------------------------------------
#define BATCH   32
#define HW      32
#define C_DIM   384
#define NHEADS  12
#define HEADD   32
#define WS      8
#define SS      4
#define NTOK    64
#define M_TOK   (BATCH * HW * HW)      // 32768
#define QKV_N   (3 * C_DIM)            // 1152
#define HIDDEN  (4 * C_DIM)            // 1536
#define SCALE_ATTN 0.17677669529663687f

// ---------------------------------------------------------------------------
// Scratch (device globals; allocation is forbidden)
// ---------------------------------------------------------------------------
__device__ __align__(16) __nv_bfloat16 g_xw_h [(size_t)M_TOK * C_DIM];
__device__ __align__(16) __nv_bfloat16 g_xw_l [(size_t)M_TOK * C_DIM];
__device__ __align__(16) float         g_qkv  [(size_t)M_TOK * QKV_N];
__device__ __align__(16) __nv_bfloat16 g_at_h [(size_t)M_TOK * C_DIM];
__device__ __align__(16) __nv_bfloat16 g_at_l [(size_t)M_TOK * C_DIM];
__device__ __align__(16) float         g_x1   [(size_t)M_TOK * C_DIM];
__device__ __align__(16) __nv_bfloat16 g_n2_h [(size_t)M_TOK * C_DIM];
__device__ __align__(16) __nv_bfloat16 g_n2_l [(size_t)M_TOK * C_DIM];
__device__ __align__(16) __nv_bfloat16 g_h_h  [(size_t)M_TOK * HIDDEN];
__device__ __align__(16) __nv_bfloat16 g_h_l  [(size_t)M_TOK * HIDDEN];
// transposed split weights [N][K]
__device__ __align__(16) __nv_bfloat16 g_wqkv_h[(size_t)QKV_N * C_DIM];
__device__ __align__(16) __nv_bfloat16 g_wqkv_l[(size_t)QKV_N * C_DIM];
__device__ __align__(16) __nv_bfloat16 g_wpr_h [(size_t)C_DIM * C_DIM];
__device__ __align__(16) __nv_bfloat16 g_wpr_l [(size_t)C_DIM * C_DIM];
__device__ __align__(16) __nv_bfloat16 g_wf1_h [(size_t)HIDDEN * C_DIM];
__device__ __align__(16) __nv_bfloat16 g_wf1_l [(size_t)HIDDEN * C_DIM];
__device__ __align__(16) __nv_bfloat16 g_wf2_h [(size_t)C_DIM * HIDDEN];
__device__ __align__(16) __nv_bfloat16 g_wf2_l [(size_t)C_DIM * HIDDEN];

// ---------------------------------------------------------------------------
// helpers
// ---------------------------------------------------------------------------
__device__ __forceinline__ int win2img(int row) {
    int w  = row >> 6;
    int n  = row & 63;
    int b  = w >> 4;
    int wi = w & 15;
    int wh = wi >> 2, ww = wi & 3;
    int r  = n >> 3,  cc = n & 7;
    int i  = (wh * 8 + r + SS) & 31;
    int j  = (ww * 8 + cc + SS) & 31;
    return b * 1024 + i * 32 + j;
}

__device__ __forceinline__ float gelu_tanh(float x) {
    float x3 = x * x * x;
    return 0.5f * x * (1.0f + tanhf(0.7978845608028654f * (x + 0.044715f * x3)));
}

__device__ __forceinline__ uint32_t smem_u32(const void* p) {
    uint32_t a;
    asm("{ .reg .u64 t; cvta.to.shared.u64 t, %1; cvt.u32.u64 %0, t; }" : "=r"(a) : "l"(p));
    return a;
}

__device__ __forceinline__ uint32_t pk2(__nv_bfloat16 a, __nv_bfloat16 b) {
    return (uint32_t)__bfloat16_as_ushort(a) | ((uint32_t)__bfloat16_as_ushort(b) << 16);
}

__device__ __forceinline__ void ldmA(uint32_t* r, uint32_t a) {
    asm volatile("ldmatrix.sync.aligned.m8n8.x4.shared.b16 {%0,%1,%2,%3}, [%4];"
                 : "=r"(r[0]), "=r"(r[1]), "=r"(r[2]), "=r"(r[3]) : "r"(a));
}
__device__ __forceinline__ void ldmB(uint32_t* r, uint32_t a) {
    asm volatile("ldmatrix.sync.aligned.m8n8.x2.shared.b16 {%0,%1}, [%2];"
                 : "=r"(r[0]), "=r"(r[1]) : "r"(a));
}
__device__ __forceinline__ void mma16816(float* c, const uint32_t* a, const uint32_t* b) {
    asm volatile("mma.sync.aligned.m16n8k16.row.col.f32.bf16.bf16.f32 "
                 "{%0,%1,%2,%3}, {%4,%5,%6,%7}, {%8,%9}, {%0,%1,%2,%3};"
                 : "+f"(c[0]), "+f"(c[1]), "+f"(c[2]), "+f"(c[3])
                 : "r"(a[0]), "r"(a[1]), "r"(a[2]), "r"(a[3]), "r"(b[0]), "r"(b[1]));
}

// ---------------------------------------------------------------------------
// weight convert: w[K,N] fp32 -> hi/lo bf16, transposed to [N,K]
// ---------------------------------------------------------------------------
__global__ void wconv_kernel(const float* __restrict__ w,
                             __nv_bfloat16* __restrict__ hi,
                             __nv_bfloat16* __restrict__ lo, int K, int N) {
    int idx = blockIdx.x * 256 + threadIdx.x;
    if (idx >= K * N) return;
    int k = idx / N, n = idx - k * N;
    float v = w[idx];
    __nv_bfloat16 h = __float2bfloat16(v);
    hi[(size_t)n * K + k] = h;
    lo[(size_t)n * K + k] = __float2bfloat16(v - __bfloat162float(h));
}

// ---------------------------------------------------------------------------
// LayerNorm -> split bf16 output. SHIFT gathers the shifted-window permutation.
// ---------------------------------------------------------------------------
template <bool SHIFT>
__global__ void ln_kernel(const float* __restrict__ x,
                          const float* __restrict__ gamma,
                          const float* __restrict__ beta,
                          __nv_bfloat16* __restrict__ oh,
                          __nv_bfloat16* __restrict__ ol) {
    int row = blockIdx.x;
    int src = SHIFT ? win2img(row) : row;
    const float* xp = x + (size_t)src * C_DIM;
    int tid = threadIdx.x;

    float v0 = xp[tid], v1 = xp[tid + 128], v2 = xp[tid + 256];
    float s  = v0 + v1 + v2;
    float sq = v0 * v0 + v1 * v1 + v2 * v2;
    #pragma unroll
    for (int o = 16; o > 0; o >>= 1) {
        s  += __shfl_down_sync(0xffffffffu, s,  o);
        sq += __shfl_down_sync(0xffffffffu, sq, o);
    }
    __shared__ float sa[4], sb[4];
    int wp = tid >> 5, ln = tid & 31;
    if (ln == 0) { sa[wp] = s; sb[wp] = sq; }
    __syncthreads();
    s  = sa[0] + sa[1] + sa[2] + sa[3];
    sq = sb[0] + sb[1] + sb[2] + sb[3];

    float mean = s * (1.0f / C_DIM);
    float var  = sq * (1.0f / C_DIM) - mean * mean;
    float inv  = rsqrtf(var + 1e-5f);

    size_t rb = (size_t)row * C_DIM;
    #pragma unroll
    for (int u = 0; u < 3; u++) {
        int c = tid + u * 128;
        float v = (u == 0 ? v0 : u == 1 ? v1 : v2);
        float y = (v - mean) * inv * gamma[c] + beta[c];
        __nv_bfloat16 h = __float2bfloat16(y);
        oh[rb + c] = h;
        ol[rb + c] = __float2bfloat16(y - __bfloat162float(h));
    }
}

// ---------------------------------------------------------------------------
// HMMA split-bf16 GEMM: C = A[M,K] @ Bt[N,K]^T (+ bias + epilogue).
// 3 passes into the same fp32 accum: Ah*Bh + Ah*Bl + Al*Bh.
// CTA tile 128x64, BK=64, 256 threads (8 warps, 4(M)x2(N), warp tile 32x32).
// EPI 0: f32 out + bias                            (qkv)
// EPI 1: bias + gelu -> split bf16 out             (fc1)
// EPI 2: bias + res[m] -> f32 out                  (fc2 + residual, final)
// EPI 3: bias + res[win2img(m)] -> f32 scattered   (proj + reverse + residual)
// ---------------------------------------------------------------------------
#define AS_STRIDE 72                       // bf16 elems per row (64 + 8 pad)
#define OFF_AH 0
#define OFF_AL (128 * AS_STRIDE * 2)       // 18432
#define OFF_BH (2 * 128 * AS_STRIDE * 2)   // 36864
#define OFF_BL (OFF_BH + 64 * AS_STRIDE * 2)
#define SMEM_BYTES (OFF_BL + 64 * AS_STRIDE * 2)   // 55296

template <int EPI>
__global__ __launch_bounds__(256)
void hgemm(const __nv_bfloat16* __restrict__ Ah, const __nv_bfloat16* __restrict__ Al,
           const __nv_bfloat16* __restrict__ Bh, const __nv_bfloat16* __restrict__ Bl,
           const float* __restrict__ bias, const float* __restrict__ res,
           float* __restrict__ Cf,
           __nv_bfloat16* __restrict__ Chi, __nv_bfloat16* __restrict__ Clo,
           int N, int K) {
    extern __shared__ __align__(16) char sm[];
    uint32_t sb = smem_u32(sm);

    int tid  = threadIdx.x;
    int lane = tid & 31;
    int wid  = tid >> 5;
    int warp_m = wid >> 1;       // 0..3
    int warp_n = wid & 1;        // 0..1
    int bm = blockIdx.y * 128, bn = blockIdx.x * 64;

    // ldmatrix per-lane addressing
    int quad = lane >> 3, lr = lane & 7;
    int aRow = warp_m * 32 + (quad & 1) * 8 + lr;
    int aCol = (quad >> 1) * 8;
    int bRow = warp_n * 32 + lr;
    int bCol = ((lane >> 3) & 1) * 8;

    float acc[2][4][4];
    #pragma unroll
    for (int i = 0; i < 2; i++)
        #pragma unroll
        for (int j = 0; j < 4; j++)
            #pragma unroll
            for (int e = 0; e < 4; e++) acc[i][j][e] = 0.0f;

    int ntile = K >> 6;
    for (int t = 0; t < ntile; t++) {
        int k0 = t << 6;
        // load A tile 128x64 hi/lo (4 uint4 each per thread)
        #pragma unroll
        for (int it = 0; it < 4; it++) {
            int f = it * 256 + tid;
            int row = f >> 3, seg = f & 7;
            size_t g = (((size_t)(bm + row) * K + k0) >> 3) + seg;
            uint32_t so = row * (AS_STRIDE * 2) + seg * 16;
            *(uint4*)(sm + OFF_AH + so) = __ldg((const uint4*)Ah + g);
            *(uint4*)(sm + OFF_AL + so) = __ldg((const uint4*)Al + g);
        }
        // load B tile 64x64 hi/lo (2 uint4 each per thread)
        #pragma unroll
        for (int it = 0; it < 2; it++) {
            int f = it * 256 + tid;
            int row = f >> 3, seg = f & 7;
            size_t g = (((size_t)(bn + row) * K + k0) >> 3) + seg;
            uint32_t so = row * (AS_STRIDE * 2) + seg * 16;
            *(uint4*)(sm + OFF_BH + so) = __ldg((const uint4*)Bh + g);
            *(uint4*)(sm + OFF_BL + so) = __ldg((const uint4*)Bl + g);
        }
        __syncthreads();

        #pragma unroll
        for (int ks = 0; ks < 4; ks++) {
            uint32_t aBase = sb + (uint32_t)((aRow * AS_STRIDE + ks * 16 + aCol) * 2);
            uint32_t bBase = sb + (uint32_t)((bRow * AS_STRIDE + ks * 16 + bCol) * 2);
            uint32_t ah[2][4], al[2][4], bh[4][2], bl[4][2];
            #pragma unroll
            for (int mt = 0; mt < 2; mt++) {
                uint32_t off = (uint32_t)(mt * 16 * AS_STRIDE * 2);
                ldmA(ah[mt], aBase + OFF_AH + off);
                ldmA(al[mt], aBase + OFF_AL + off);
            }
            #pragma unroll
            for (int nt = 0; nt < 4; nt++) {
                uint32_t off = (uint32_t)(nt * 8 * AS_STRIDE * 2);
                ldmB(bh[nt], bBase + OFF_BH + off);
                ldmB(bl[nt], bBase + OFF_BL + off);
            }
            #pragma unroll
            for (int mt = 0; mt < 2; mt++)
                #pragma unroll
                for (int nt = 0; nt < 4; nt++) {
                    mma16816(acc[mt][nt], ah[mt], bh[nt]);
                    mma16816(acc[mt][nt], ah[mt], bl[nt]);
                    mma16816(acc[mt][nt], al[mt], bh[nt]);
                }
        }
        __syncthreads();
    }

    // epilogue: c0,c1 at (row, col..col+1); c2,c3 at (row+8, col..col+1)
    #pragma unroll
    for (int mt = 0; mt < 2; mt++) {
        int row0 = bm + warp_m * 32 + mt * 16 + (lane >> 2);
        #pragma unroll
        for (int half = 0; half < 2; half++) {
            int row  = row0 + half * 8;
            int orow = (EPI == 3) ? win2img(row) : row;
            #pragma unroll
            for (int nt = 0; nt < 4; nt++) {
                int col = bn + warp_n * 32 + nt * 8 + (lane & 3) * 2;
                float c0 = acc[mt][nt][half * 2 + 0] + bias[col];
                float c1 = acc[mt][nt][half * 2 + 1] + bias[col + 1];
                if (EPI == 1) {
                    c0 = gelu_tanh(c0);
                    c1 = gelu_tanh(c1);
                    __nv_bfloat16 h0 = __float2bfloat16(c0);
                    __nv_bfloat16 h1 = __float2bfloat16(c1);
                    __nv_bfloat16 l0 = __float2bfloat16(c0 - __bfloat162float(h0));
                    __nv_bfloat16 l1 = __float2bfloat16(c1 - __bfloat162float(h1));
                    size_t o = (size_t)row * N + col;
                    *(uint32_t*)&Chi[o] = pk2(h0, h1);
                    *(uint32_t*)&Clo[o] = pk2(l0, l1);
                } else {
                    size_t o = (size_t)orow * N + col;
                    if (EPI == 2 || EPI == 3) { c0 += res[o]; c1 += res[o + 1]; }
                    *(float2*)&Cf[o] = make_float2(c0, c1);
                }
            }
        }
    }
}

// ---------------------------------------------------------------------------
// Windowed attention (SIMT). Writes split bf16 (proj's A operand).
// ---------------------------------------------------------------------------
__global__ __launch_bounds__(128)
void attn_kernel(const float* __restrict__ qkv,
                 const float* __restrict__ table,
                 __nv_bfloat16* __restrict__ oh,
                 __nv_bfloat16* __restrict__ ol) {
    __shared__ float qs[64][33];
    __shared__ float ks[64][33];
    __shared__ float vs[64][32];
    __shared__ float S[64][64];
    __shared__ int   cnt[64];

    int blk = blockIdx.x;
    int w   = blk / NHEADS;
    int h   = blk - w * NHEADS;
    int tid = threadIdx.x;

    const float* base = qkv + (size_t)w * NTOK * QKV_N + h * HEADD;
    for (int f = tid; f < 512; f += 128) {
        int n = f >> 3;
        int d = (f & 7) * 4;
        float4 qv = *(const float4*)&base[(size_t)n * QKV_N + d];
        float4 kv = *(const float4*)&base[(size_t)n * QKV_N + C_DIM + d];
        float4 vv = *(const float4*)&base[(size_t)n * QKV_N + 2 * C_DIM + d];
        qs[n][d + 0] = qv.x * SCALE_ATTN; qs[n][d + 1] = qv.y * SCALE_ATTN;
        qs[n][d + 2] = qv.z * SCALE_ATTN; qs[n][d + 3] = qv.w * SCALE_ATTN;
        ks[n][d + 0] = kv.x; ks[n][d + 1] = kv.y;
        ks[n][d + 2] = kv.z; ks[n][d + 3] = kv.w;
        *(float4*)&vs[n][d] = vv;
    }
    if (tid < 64) {
        int wi = w & 15;
        int wh = wi >> 2, ww = wi & 3;
        int i = wh * 8 + (tid >> 3);
        int j = ww * 8 + (tid & 7);
        int ri = (i < 24) ? 0 : ((i < 28) ? 1 : 2);
        int rj = (j < 24) ? 0 : ((j < 28) ? 1 : 2);
        cnt[tid] = ri * 3 + rj;
    }
    __syncthreads();

    for (int e = tid; e < 1024; e += 128) {
        int n  = e >> 4;
        int m0 = (e & 15) * 4;
        float s0 = 0.f, s1 = 0.f, s2 = 0.f, s3 = 0.f;
        #pragma unroll
        for (int d = 0; d < 32; d++) {
            float q = qs[n][d];
            s0 = fmaf(q, ks[m0 + 0][d], s0);
            s1 = fmaf(q, ks[m0 + 1][d], s1);
            s2 = fmaf(q, ks[m0 + 2][d], s2);
            s3 = fmaf(q, ks[m0 + 3][d], s3);
        }
        int r1 = n >> 3, c1 = n & 7;
        int cn = cnt[n];
        #pragma unroll
        for (int u = 0; u < 4; u++) {
            int m  = m0 + u;
            int r2 = m >> 3, c2 = m & 7;
            int rel = (r1 - r2 + 7) * 15 + (c1 - c2 + 7);
            float s = (u == 0 ? s0 : u == 1 ? s1 : u == 2 ? s2 : s3);
            s += __ldg(&table[rel * NHEADS + h]);
            if (cn != cnt[m]) s -= 100.0f;
            S[n][m] = s;
        }
    }
    __syncthreads();

    int wp = tid >> 5, ln = tid & 31;
    for (int r = wp; r < 64; r += 4) {
        float a0 = S[r][ln], a1 = S[r][ln + 32];
        float mx = fmaxf(a0, a1);
        #pragma unroll
        for (int o = 16; o > 0; o >>= 1) mx = fmaxf(mx, __shfl_xor_sync(0xffffffffu, mx, o));
        a0 = __expf(a0 - mx);
        a1 = __expf(a1 - mx);
        float sm = a0 + a1;
        #pragma unroll
        for (int o = 16; o > 0; o >>= 1) sm += __shfl_xor_sync(0xffffffffu, sm, o);
        float inv = 1.0f / sm;
        S[r][ln] = a0 * inv;
        S[r][ln + 32] = a1 * inv;
    }
    __syncthreads();

    for (int e = tid; e < 512; e += 128) {
        int n  = e >> 3;
        int d0 = (e & 7) * 4;
        float sx = 0.f, sy = 0.f, sz = 0.f, sw = 0.f;
        #pragma unroll
        for (int m = 0; m < 64; m++) {
            float p = S[n][m];
            float4 vv = *(const float4*)&vs[m][d0];
            sx = fmaf(p, vv.x, sx); sy = fmaf(p, vv.y, sy);
            sz = fmaf(p, vv.z, sz); sw = fmaf(p, vv.w, sw);
        }
        __nv_bfloat16 h0 = __float2bfloat16(sx), h1 = __float2bfloat16(sy);
        __nv_bfloat16 h2 = __float2bfloat16(sz), h3 = __float2bfloat16(sw);
        __nv_bfloat16 l0 = __float2bfloat16(sx - __bfloat162float(h0));
        __nv_bfloat16 l1 = __float2bfloat16(sy - __bfloat162float(h1));
        __nv_bfloat16 l2 = __float2bfloat16(sz - __bfloat162float(h2));
        __nv_bfloat16 l3 = __float2bfloat16(sw - __bfloat162float(h3));
        size_t o = (size_t)(w * NTOK + n) * C_DIM + h * HEADD + d0;
        *(uint2*)&oh[o] = make_uint2(pk2(h0, h1), pk2(h2, h3));
        *(uint2*)&ol[o] = make_uint2(pk2(l0, l1), pk2(l2, l3));
    }
}

// ---------------------------------------------------------------------------
// launch
// ---------------------------------------------------------------------------
extern "C" void kernel_launch(void* const* d_in, const int* in_sizes, int n_in,
                              void* d_out, int out_size) {
    const float* x      = (const float*)d_in[0];
    const float* n1g    = (const float*)d_in[1];
    const float* n1b    = (const float*)d_in[2];
    const float* qkv_w  = (const float*)d_in[3];
    const float* qkv_b  = (const float*)d_in[4];
    const float* table  = (const float*)d_in[5];
    const float* proj_w = (const float*)d_in[6];
    const float* proj_b = (const float*)d_in[7];
    const float* n2g    = (const float*)d_in[8];
    const float* n2b    = (const float*)d_in[9];
    const float* fc1_w  = (const float*)d_in[10];
    const float* fc1_b  = (const float*)d_in[11];
    const float* fc2_w  = (const float*)d_in[12];
    const float* fc2_b  = (const float*)d_in[13];
    float* out = (float*)d_out;

    static __nv_bfloat16 *xw_h, *xw_l, *at_h, *at_l, *n2_h, *n2_l, *h_h, *h_l;
    static __nv_bfloat16 *wqkv_h, *wqkv_l, *wpr_h, *wpr_l, *wf1_h, *wf1_l, *wf2_h, *wf2_l;
    static float *qkvb, *x1;
    static bool init = false;
    if (!init) {
        init = true;
        cudaGetSymbolAddress((void**)&xw_h, g_xw_h);  cudaGetSymbolAddress((void**)&xw_l, g_xw_l);
        cudaGetSymbolAddress((void**)&at_h, g_at_h);  cudaGetSymbolAddress((void**)&at_l, g_at_l);
        cudaGetSymbolAddress((void**)&n2_h, g_n2_h);  cudaGetSymbolAddress((void**)&n2_l, g_n2_l);
        cudaGetSymbolAddress((void**)&h_h,  g_h_h);   cudaGetSymbolAddress((void**)&h_l,  g_h_l);
        cudaGetSymbolAddress((void**)&wqkv_h, g_wqkv_h); cudaGetSymbolAddress((void**)&wqkv_l, g_wqkv_l);
        cudaGetSymbolAddress((void**)&wpr_h,  g_wpr_h);  cudaGetSymbolAddress((void**)&wpr_l,  g_wpr_l);
        cudaGetSymbolAddress((void**)&wf1_h,  g_wf1_h);  cudaGetSymbolAddress((void**)&wf1_l,  g_wf1_l);
        cudaGetSymbolAddress((void**)&wf2_h,  g_wf2_h);  cudaGetSymbolAddress((void**)&wf2_l,  g_wf2_l);
        cudaGetSymbolAddress((void**)&qkvb, g_qkv);
        cudaGetSymbolAddress((void**)&x1,   g_x1);
        cudaFuncSetAttribute(hgemm<0>, cudaFuncAttributeMaxDynamicSharedMemorySize, SMEM_BYTES);
        cudaFuncSetAttribute(hgemm<1>, cudaFuncAttributeMaxDynamicSharedMemorySize, SMEM_BYTES);
        cudaFuncSetAttribute(hgemm<2>, cudaFuncAttributeMaxDynamicSharedMemorySize, SMEM_BYTES);
        cudaFuncSetAttribute(hgemm<3>, cudaFuncAttributeMaxDynamicSharedMemorySize, SMEM_BYTES);
    }

    // 0) weight convert + transpose + split
    wconv_kernel<<<(C_DIM * QKV_N + 255) / 256, 256>>>(qkv_w, wqkv_h, wqkv_l, C_DIM, QKV_N);
    wconv_kernel<<<(C_DIM * C_DIM + 255) / 256, 256>>>(proj_w, wpr_h, wpr_l, C_DIM, C_DIM);
    wconv_kernel<<<(C_DIM * HIDDEN + 255) / 256, 256>>>(fc1_w, wf1_h, wf1_l, C_DIM, HIDDEN);
    wconv_kernel<<<(HIDDEN * C_DIM + 255) / 256, 256>>>(fc2_w, wf2_h, wf2_l, HIDDEN, C_DIM);

    // 1) LN1 + shift + window partition -> split bf16
    ln_kernel<true><<<M_TOK, 128>>>(x, n1g, n1b, xw_h, xw_l);

    // 2) QKV GEMM (f32 out)
    {
        dim3 grid(QKV_N / 64, M_TOK / 128);
        hgemm<0><<<grid, 256, SMEM_BYTES>>>(xw_h, xw_l, wqkv_h, wqkv_l, qkv_b,
                                            nullptr, qkvb, nullptr, nullptr,
                                            QKV_N, C_DIM);
    }

    // 3) windowed attention -> split bf16
    attn_kernel<<<512 * NHEADS, 128>>>(qkvb, table, at_h, at_l);

    // 4) proj + reverse/unshift scatter + residual -> x1 (f32, image layout)
    {
        dim3 grid(C_DIM / 64, M_TOK / 128);
        hgemm<3><<<grid, 256, SMEM_BYTES>>>(at_h, at_l, wpr_h, wpr_l, proj_b,
                                            x, x1, nullptr, nullptr,
                                            C_DIM, C_DIM);
    }

    // 5) LN2 -> split bf16
    ln_kernel<false><<<M_TOK, 128>>>(x1, n2g, n2b, n2_h, n2_l);

    // 6) FC1 + GELU -> split bf16
    {
        dim3 grid(HIDDEN / 64, M_TOK / 128);
        hgemm<1><<<grid, 256, SMEM_BYTES>>>(n2_h, n2_l, wf1_h, wf1_l, fc1_b,
                                            nullptr, nullptr, h_h, h_l,
                                            HIDDEN, C_DIM);
    }

    // 7) FC2 + residual -> out (f32)
    {
        dim3 grid(C_DIM / 64, M_TOK / 128);
        hgemm<2><<<grid, 256, SMEM_BYTES>>>(h_h, h_l, wf2_h, wf2_l, fc2_b,
                                            x1, out, nullptr, nullptr,
                                            C_DIM, HIDDEN);
    }
}

// round 8
// speedup vs baseline: 3.5674x; 1.7958x over previous
#include <cuda_runtime.h>
#include <cuda_fp16.h>
#include <math.h>
#include <stdint.h>

// ---------------------------------------------------------------------------
// Problem constants
// ---------------------------------------------------------------------------
#define BATCH   32
#define HW      32
#define C_DIM   384
#define NHEADS  12
#define HEADD   32
#define WS      8
#define SS      4
#define NTOK    64
#define M_TOK   (BATCH * HW * HW)      // 32768
#define QKV_N   (3 * C_DIM)            // 1152
#define HIDDEN  (4 * C_DIM)            // 1536
#define SCALE_ATTN 0.17677669529663687f

// ---------------------------------------------------------------------------
// Scratch (device globals; allocation is forbidden)
// ---------------------------------------------------------------------------
__device__ __align__(16) __half g_xw  [(size_t)M_TOK * C_DIM];
__device__ __align__(16) float  g_qkv [(size_t)M_TOK * QKV_N];
__device__ __align__(16) __half g_at  [(size_t)M_TOK * C_DIM];
__device__ __align__(16) float  g_x1  [(size_t)M_TOK * C_DIM];
__device__ __align__(16) __half g_n2  [(size_t)M_TOK * C_DIM];
__device__ __align__(16) __half g_h   [(size_t)M_TOK * HIDDEN];
// transposed fp16 weights [N][K]
__device__ __align__(16) __half g_wqkv[(size_t)QKV_N * C_DIM];
__device__ __align__(16) __half g_wpr [(size_t)C_DIM * C_DIM];
__device__ __align__(16) __half g_wf1 [(size_t)HIDDEN * C_DIM];
__device__ __align__(16) __half g_wf2 [(size_t)C_DIM * HIDDEN];

// ---------------------------------------------------------------------------
// helpers
// ---------------------------------------------------------------------------
__device__ __forceinline__ int win2img(int row) {
    int w  = row >> 6;
    int n  = row & 63;
    int b  = w >> 4;
    int wi = w & 15;
    int wh = wi >> 2, ww = wi & 3;
    int r  = n >> 3,  cc = n & 7;
    int i  = (wh * 8 + r + SS) & 31;
    int j  = (ww * 8 + cc + SS) & 31;
    return b * 1024 + i * 32 + j;
}

__device__ __forceinline__ float gelu_tanh(float x) {
    float x3 = x * x * x;
    return 0.5f * x * (1.0f + tanhf(0.7978845608028654f * (x + 0.044715f * x3)));
}

__device__ __forceinline__ uint32_t smem_u32(const void* p) {
    uint32_t a;
    asm("{ .reg .u64 t; cvta.to.shared.u64 t, %1; cvt.u32.u64 %0, t; }" : "=r"(a) : "l"(p));
    return a;
}

__device__ __forceinline__ uint32_t pkh2(__half a, __half b) {
    return (uint32_t)__half_as_ushort(a) | ((uint32_t)__half_as_ushort(b) << 16);
}

__device__ __forceinline__ void cpasync16(uint32_t dst, const void* src) {
    asm volatile("cp.async.cg.shared.global [%0], [%1], 16;" :: "r"(dst), "l"(src));
}

__device__ __forceinline__ void ldm4(uint32_t* r, uint32_t a) {
    asm volatile("ldmatrix.sync.aligned.m8n8.x4.shared.b16 {%0,%1,%2,%3}, [%4];"
                 : "=r"(r[0]), "=r"(r[1]), "=r"(r[2]), "=r"(r[3]) : "r"(a));
}
__device__ __forceinline__ void mma16816(float* c, const uint32_t* a, const uint32_t* b) {
    asm volatile("mma.sync.aligned.m16n8k16.row.col.f32.f16.f16.f32 "
                 "{%0,%1,%2,%3}, {%4,%5,%6,%7}, {%8,%9}, {%0,%1,%2,%3};"
                 : "+f"(c[0]), "+f"(c[1]), "+f"(c[2]), "+f"(c[3])
                 : "r"(a[0]), "r"(a[1]), "r"(a[2]), "r"(a[3]), "r"(b[0]), "r"(b[1]));
}

// ---------------------------------------------------------------------------
// weight convert: w[K,N] fp32 -> fp16, transposed to [N,K]
// ---------------------------------------------------------------------------
__global__ void wconv_kernel(const float* __restrict__ w,
                             __half* __restrict__ o, int K, int N) {
    int idx = blockIdx.x * 256 + threadIdx.x;
    if (idx >= K * N) return;
    int k = idx / N, n = idx - k * N;
    o[(size_t)n * K + k] = __float2half_rn(w[idx]);
}

// ---------------------------------------------------------------------------
// LayerNorm -> fp16. SHIFT gathers the shifted-window permutation.
// ---------------------------------------------------------------------------
template <bool SHIFT>
__global__ void ln_kernel(const float* __restrict__ x,
                          const float* __restrict__ gamma,
                          const float* __restrict__ beta,
                          __half* __restrict__ o) {
    int row = blockIdx.x;
    int src = SHIFT ? win2img(row) : row;
    const float* xp = x + (size_t)src * C_DIM;
    int tid = threadIdx.x;

    float v0 = xp[tid], v1 = xp[tid + 128], v2 = xp[tid + 256];
    float s  = v0 + v1 + v2;
    float sq = v0 * v0 + v1 * v1 + v2 * v2;
    #pragma unroll
    for (int off = 16; off > 0; off >>= 1) {
        s  += __shfl_down_sync(0xffffffffu, s,  off);
        sq += __shfl_down_sync(0xffffffffu, sq, off);
    }
    __shared__ float sa[4], sb[4];
    int wp = tid >> 5, ln = tid & 31;
    if (ln == 0) { sa[wp] = s; sb[wp] = sq; }
    __syncthreads();
    s  = sa[0] + sa[1] + sa[2] + sa[3];
    sq = sb[0] + sb[1] + sb[2] + sb[3];

    float mean = s * (1.0f / C_DIM);
    float var  = sq * (1.0f / C_DIM) - mean * mean;
    float inv  = rsqrtf(var + 1e-5f);

    size_t rb = (size_t)row * C_DIM;
    #pragma unroll
    for (int u = 0; u < 3; u++) {
        int c = tid + u * 128;
        float v = (u == 0 ? v0 : u == 1 ? v1 : v2);
        o[rb + c] = __float2half_rn((v - mean) * inv * gamma[c] + beta[c]);
    }
}

// ---------------------------------------------------------------------------
// fp16 HMMA GEMM: C = A[M,K] @ Bt[N,K]^T (+ bias + epilogue), fp32 accum.
// CTA tile 128x128, BK=64, 256 threads (8 warps 4x2, warp tile 32x64).
// cp.async 2-stage pipelined mainloop.
// EPI 0: f32 out + bias                            (qkv)
// EPI 1: bias + gelu -> fp16 out                   (fc1)
// EPI 2: bias + res[m] -> f32 out                  (fc2 + residual, final)
// EPI 3: bias + res[win2img(m)] -> f32 scattered   (proj + reverse + residual)
// ---------------------------------------------------------------------------
#define AS_STRIDE 72                      // halfs per row (64 + 8 pad) = 144 B
#define TILE_BYTES (128 * AS_STRIDE * 2)  // 18432 per tile
#define STAGE_BYTES (2 * TILE_BYTES)      // A + B
#define SMEM_BYTES (2 * STAGE_BYTES)      // 73728

template <int EPI>
__global__ __launch_bounds__(256)
void hgemm(const __half* __restrict__ A, const __half* __restrict__ B,
           const float* __restrict__ bias, const float* __restrict__ res,
           float* __restrict__ Cf, __half* __restrict__ Ch,
           int N, int K) {
    extern __shared__ __align__(16) char sm[];
    uint32_t sb = smem_u32(sm);

    int tid  = threadIdx.x;
    int lane = tid & 31;
    int wid  = tid >> 5;
    int warp_m = wid >> 1;       // 0..3 -> 32 rows
    int warp_n = wid & 1;        // 0..1 -> 64 cols
    int bm = blockIdx.y * 128, bn = blockIdx.x * 128;

    // ldmatrix lane addressing
    int lr = lane & 7;
    int aRow = warp_m * 32 + ((lane >> 3) & 1) * 8 + lr;   // + mt*16
    int aCol = (lane >> 4) * 8;
    int bRow = warp_n * 64 + ((lane >> 4) & 1) * 8 + lr;   // + ntp*16
    int bCol = ((lane >> 3) & 1) * 8;

    float acc[2][8][4];
    #pragma unroll
    for (int i = 0; i < 2; i++)
        #pragma unroll
        for (int j = 0; j < 8; j++)
            #pragma unroll
            for (int e = 0; e < 4; e++) acc[i][j][e] = 0.0f;

    int ntile = K >> 6;

    // stage loader: 4 A-chunks + 4 B-chunks per thread
    int ldRow = tid >> 3;            // 0..31 (x4 iterations -> 128 rows)
    int ldSeg = tid & 7;
    #define LOAD_STAGE(t, s)                                                        \
    do {                                                                            \
        int k0_ = (t) << 6;                                                         \
        uint32_t dstA = sb + (s) * STAGE_BYTES + ldRow * 144 + ldSeg * 16;          \
        uint32_t dstB = dstA + TILE_BYTES;                                          \
        _Pragma("unroll")                                                           \
        for (int it = 0; it < 4; it++) {                                            \
            int row = ldRow + it * 32;                                              \
            cpasync16(dstA + it * 32 * 144,                                         \
                      (const uint4*)A + (((size_t)(bm + row) * K + k0_) >> 3) + ldSeg); \
            cpasync16(dstB + it * 32 * 144,                                         \
                      (const uint4*)B + (((size_t)(bn + row) * K + k0_) >> 3) + ldSeg); \
        }                                                                           \
        asm volatile("cp.async.commit_group;");                                     \
    } while (0)

    LOAD_STAGE(0, 0);

    for (int t = 0; t < ntile; t++) {
        if (t + 1 < ntile) {
            LOAD_STAGE(t + 1, (t + 1) & 1);
            asm volatile("cp.async.wait_group 1;");
        } else {
            asm volatile("cp.async.wait_group 0;");
        }
        __syncthreads();

        uint32_t offA = sb + (t & 1) * STAGE_BYTES;
        uint32_t offB = offA + TILE_BYTES;

        #pragma unroll
        for (int ks = 0; ks < 4; ks++) {
            uint32_t a[2][4], b[4][4];
            #pragma unroll
            for (int mt = 0; mt < 2; mt++)
                ldm4(a[mt], offA + (uint32_t)(((aRow + mt * 16) * AS_STRIDE) + ks * 16 + aCol) * 2);
            #pragma unroll
            for (int np = 0; np < 4; np++)
                ldm4(b[np], offB + (uint32_t)(((bRow + np * 16) * AS_STRIDE) + ks * 16 + bCol) * 2);
            #pragma unroll
            for (int mt = 0; mt < 2; mt++)
                #pragma unroll
                for (int np = 0; np < 4; np++) {
                    mma16816(acc[mt][np * 2 + 0], a[mt], &b[np][0]);
                    mma16816(acc[mt][np * 2 + 1], a[mt], &b[np][2]);
                }
        }
        __syncthreads();
    }

    // epilogue: c0,c1 at (row, col..col+1); c2,c3 at (row+8, ...)
    #pragma unroll
    for (int mt = 0; mt < 2; mt++) {
        int row0 = bm + warp_m * 32 + mt * 16 + (lane >> 2);
        #pragma unroll
        for (int half = 0; half < 2; half++) {
            int row  = row0 + half * 8;
            int orow = (EPI == 3) ? win2img(row) : row;
            #pragma unroll
            for (int nt = 0; nt < 8; nt++) {
                int col = bn + warp_n * 64 + nt * 8 + (lane & 3) * 2;
                float c0 = acc[mt][nt][half * 2 + 0] + bias[col];
                float c1 = acc[mt][nt][half * 2 + 1] + bias[col + 1];
                if (EPI == 1) {
                    c0 = gelu_tanh(c0);
                    c1 = gelu_tanh(c1);
                    *(uint32_t*)&Ch[(size_t)row * N + col] =
                        pkh2(__float2half_rn(c0), __float2half_rn(c1));
                } else {
                    size_t o = (size_t)orow * N + col;
                    if (EPI == 2 || EPI == 3) { c0 += res[o]; c1 += res[o + 1]; }
                    *(float2*)&Cf[o] = make_float2(c0, c1);
                }
            }
        }
    }
}

// ---------------------------------------------------------------------------
// Windowed attention (SIMT, fp32 in, fp16 out)
// ---------------------------------------------------------------------------
__global__ __launch_bounds__(128)
void attn_kernel(const float* __restrict__ qkv,
                 const float* __restrict__ table,
                 __half* __restrict__ oh) {
    __shared__ float qs[64][33];
    __shared__ float ks[64][33];
    __shared__ float vs[64][32];
    __shared__ float S[64][64];
    __shared__ int   cnt[64];

    int blk = blockIdx.x;
    int w   = blk / NHEADS;
    int h   = blk - w * NHEADS;
    int tid = threadIdx.x;

    const float* base = qkv + (size_t)w * NTOK * QKV_N + h * HEADD;
    for (int f = tid; f < 512; f += 128) {
        int n = f >> 3;
        int d = (f & 7) * 4;
        float4 qv = *(const float4*)&base[(size_t)n * QKV_N + d];
        float4 kv = *(const float4*)&base[(size_t)n * QKV_N + C_DIM + d];
        float4 vv = *(const float4*)&base[(size_t)n * QKV_N + 2 * C_DIM + d];
        qs[n][d + 0] = qv.x * SCALE_ATTN; qs[n][d + 1] = qv.y * SCALE_ATTN;
        qs[n][d + 2] = qv.z * SCALE_ATTN; qs[n][d + 3] = qv.w * SCALE_ATTN;
        ks[n][d + 0] = kv.x; ks[n][d + 1] = kv.y;
        ks[n][d + 2] = kv.z; ks[n][d + 3] = kv.w;
        *(float4*)&vs[n][d] = vv;
    }
    if (tid < 64) {
        int wi = w & 15;
        int wh = wi >> 2, ww = wi & 3;
        int i = wh * 8 + (tid >> 3);
        int j = ww * 8 + (tid & 7);
        int ri = (i < 24) ? 0 : ((i < 28) ? 1 : 2);
        int rj = (j < 24) ? 0 : ((j < 28) ? 1 : 2);
        cnt[tid] = ri * 3 + rj;
    }
    __syncthreads();

    for (int e = tid; e < 1024; e += 128) {
        int n  = e >> 4;
        int m0 = (e & 15) * 4;
        float s0 = 0.f, s1 = 0.f, s2 = 0.f, s3 = 0.f;
        #pragma unroll
        for (int d = 0; d < 32; d++) {
            float q = qs[n][d];
            s0 = fmaf(q, ks[m0 + 0][d], s0);
            s1 = fmaf(q, ks[m0 + 1][d], s1);
            s2 = fmaf(q, ks[m0 + 2][d], s2);
            s3 = fmaf(q, ks[m0 + 3][d], s3);
        }
        int r1 = n >> 3, c1 = n & 7;
        int cn = cnt[n];
        #pragma unroll
        for (int u = 0; u < 4; u++) {
            int m  = m0 + u;
            int r2 = m >> 3, c2 = m & 7;
            int rel = (r1 - r2 + 7) * 15 + (c1 - c2 + 7);
            float s = (u == 0 ? s0 : u == 1 ? s1 : u == 2 ? s2 : s3);
            s += __ldg(&table[rel * NHEADS + h]);
            if (cn != cnt[m]) s -= 100.0f;
            S[n][m] = s;
        }
    }
    __syncthreads();

    int wp = tid >> 5, ln = tid & 31;
    for (int r = wp; r < 64; r += 4) {
        float a0 = S[r][ln], a1 = S[r][ln + 32];
        float mx = fmaxf(a0, a1);
        #pragma unroll
        for (int o = 16; o > 0; o >>= 1) mx = fmaxf(mx, __shfl_xor_sync(0xffffffffu, mx, o));
        a0 = __expf(a0 - mx);
        a1 = __expf(a1 - mx);
        float sm = a0 + a1;
        #pragma unroll
        for (int o = 16; o > 0; o >>= 1) sm += __shfl_xor_sync(0xffffffffu, sm, o);
        float inv = 1.0f / sm;
        S[r][ln] = a0 * inv;
        S[r][ln + 32] = a1 * inv;
    }
    __syncthreads();

    for (int e = tid; e < 512; e += 128) {
        int n  = e >> 3;
        int d0 = (e & 7) * 4;
        float sx = 0.f, sy = 0.f, sz = 0.f, sw = 0.f;
        #pragma unroll
        for (int m = 0; m < 64; m++) {
            float p = S[n][m];
            float4 vv = *(const float4*)&vs[m][d0];
            sx = fmaf(p, vv.x, sx); sy = fmaf(p, vv.y, sy);
            sz = fmaf(p, vv.z, sz); sw = fmaf(p, vv.w, sw);
        }
        size_t o = (size_t)(w * NTOK + n) * C_DIM + h * HEADD + d0;
        *(uint2*)&oh[o] = make_uint2(pkh2(__float2half_rn(sx), __float2half_rn(sy)),
                                     pkh2(__float2half_rn(sz), __float2half_rn(sw)));
    }
}

// ---------------------------------------------------------------------------
// launch
// ---------------------------------------------------------------------------
extern "C" void kernel_launch(void* const* d_in, const int* in_sizes, int n_in,
                              void* d_out, int out_size) {
    const float* x      = (const float*)d_in[0];
    const float* n1g    = (const float*)d_in[1];
    const float* n1b    = (const float*)d_in[2];
    const float* qkv_w  = (const float*)d_in[3];
    const float* qkv_b  = (const float*)d_in[4];
    const float* table  = (const float*)d_in[5];
    const float* proj_w = (const float*)d_in[6];
    const float* proj_b = (const float*)d_in[7];
    const float* n2g    = (const float*)d_in[8];
    const float* n2b    = (const float*)d_in[9];
    const float* fc1_w  = (const float*)d_in[10];
    const float* fc1_b  = (const float*)d_in[11];
    const float* fc2_w  = (const float*)d_in[12];
    const float* fc2_b  = (const float*)d_in[13];
    float* out = (float*)d_out;

    static __half *xw, *at, *n2, *hbuf, *wqkv, *wpr, *wf1, *wf2;
    static float *qkvb, *x1;
    static bool init = false;
    if (!init) {
        init = true;
        cudaGetSymbolAddress((void**)&xw,   g_xw);
        cudaGetSymbolAddress((void**)&at,   g_at);
        cudaGetSymbolAddress((void**)&n2,   g_n2);
        cudaGetSymbolAddress((void**)&hbuf, g_h);
        cudaGetSymbolAddress((void**)&wqkv, g_wqkv);
        cudaGetSymbolAddress((void**)&wpr,  g_wpr);
        cudaGetSymbolAddress((void**)&wf1,  g_wf1);
        cudaGetSymbolAddress((void**)&wf2,  g_wf2);
        cudaGetSymbolAddress((void**)&qkvb, g_qkv);
        cudaGetSymbolAddress((void**)&x1,   g_x1);
        cudaFuncSetAttribute(hgemm<0>, cudaFuncAttributeMaxDynamicSharedMemorySize, SMEM_BYTES);
        cudaFuncSetAttribute(hgemm<1>, cudaFuncAttributeMaxDynamicSharedMemorySize, SMEM_BYTES);
        cudaFuncSetAttribute(hgemm<2>, cudaFuncAttributeMaxDynamicSharedMemorySize, SMEM_BYTES);
        cudaFuncSetAttribute(hgemm<3>, cudaFuncAttributeMaxDynamicSharedMemorySize, SMEM_BYTES);
    }

    // 0) weight convert + transpose (fp16)
    wconv_kernel<<<(C_DIM * QKV_N + 255) / 256, 256>>>(qkv_w, wqkv, C_DIM, QKV_N);
    wconv_kernel<<<(C_DIM * C_DIM + 255) / 256, 256>>>(proj_w, wpr, C_DIM, C_DIM);
    wconv_kernel<<<(C_DIM * HIDDEN + 255) / 256, 256>>>(fc1_w, wf1, C_DIM, HIDDEN);
    wconv_kernel<<<(HIDDEN * C_DIM + 255) / 256, 256>>>(fc2_w, wf2, HIDDEN, C_DIM);

    // 1) LN1 + shift + window partition -> fp16
    ln_kernel<true><<<M_TOK, 128>>>(x, n1g, n1b, xw);

    // 2) QKV GEMM (f32 out)
    {
        dim3 grid(QKV_N / 128, M_TOK / 128);
        hgemm<0><<<grid, 256, SMEM_BYTES>>>(xw, wqkv, qkv_b, nullptr,
                                            qkvb, nullptr, QKV_N, C_DIM);
    }

    // 3) windowed attention -> fp16
    attn_kernel<<<512 * NHEADS, 128>>>(qkvb, table, at);

    // 4) proj + reverse/unshift scatter + residual -> x1 (f32, image layout)
    {
        dim3 grid(C_DIM / 128, M_TOK / 128);
        hgemm<3><<<grid, 256, SMEM_BYTES>>>(at, wpr, proj_b, x,
                                            x1, nullptr, C_DIM, C_DIM);
    }

    // 5) LN2 -> fp16
    ln_kernel<false><<<M_TOK, 128>>>(x1, n2g, n2b, n2);

    // 6) FC1 + GELU -> fp16
    {
        dim3 grid(HIDDEN / 128, M_TOK / 128);
        hgemm<1><<<grid, 256, SMEM_BYTES>>>(n2, wf1, fc1_b, nullptr,
                                            nullptr, hbuf, HIDDEN, C_DIM);
    }

    // 7) FC2 + residual -> out (f32)
    {
        dim3 grid(C_DIM / 128, M_TOK / 128);
        hgemm<2><<<grid, 256, SMEM_BYTES>>>(hbuf, wf2, fc2_b, x1,
                                            out, nullptr, C_DIM, HIDDEN);
    }
}

// round 9
// speedup vs baseline: 5.6305x; 1.5783x over previous
#include <cuda_runtime.h>
#include <cuda_fp16.h>
#include <math.h>
#include <stdint.h>

// ---------------------------------------------------------------------------
// Problem constants
// ---------------------------------------------------------------------------
#define BATCH   32
#define HW      32
#define C_DIM   384
#define NHEADS  12
#define HEADD   32
#define WS      8
#define SS      4
#define NTOK    64
#define M_TOK   (BATCH * HW * HW)      // 32768
#define QKV_N   (3 * C_DIM)            // 1152
#define HIDDEN  (4 * C_DIM)            // 1536
#define SCALE_ATTN 0.17677669529663687f

// ---------------------------------------------------------------------------
// Scratch (device globals; allocation is forbidden)
// ---------------------------------------------------------------------------
__device__ __align__(16) __half g_xw  [(size_t)M_TOK * C_DIM];
__device__ __align__(16) __half g_qkv [(size_t)M_TOK * QKV_N];
__device__ __align__(16) __half g_at  [(size_t)M_TOK * C_DIM];
__device__ __align__(16) float  g_x1  [(size_t)M_TOK * C_DIM];
__device__ __align__(16) __half g_n2  [(size_t)M_TOK * C_DIM];
__device__ __align__(16) __half g_h   [(size_t)M_TOK * HIDDEN];
// transposed fp16 weights [N][K]
__device__ __align__(16) __half g_wqkv[(size_t)QKV_N * C_DIM];
__device__ __align__(16) __half g_wpr [(size_t)C_DIM * C_DIM];
__device__ __align__(16) __half g_wf1 [(size_t)HIDDEN * C_DIM];
__device__ __align__(16) __half g_wf2 [(size_t)C_DIM * HIDDEN];

// ---------------------------------------------------------------------------
// helpers
// ---------------------------------------------------------------------------
__device__ __forceinline__ int win2img(int row) {
    int w  = row >> 6;
    int n  = row & 63;
    int b  = w >> 4;
    int wi = w & 15;
    int wh = wi >> 2, ww = wi & 3;
    int r  = n >> 3,  cc = n & 7;
    int i  = (wh * 8 + r + SS) & 31;
    int j  = (ww * 8 + cc + SS) & 31;
    return b * 1024 + i * 32 + j;
}

__device__ __forceinline__ float gelu_tanh(float x) {
    float x3 = x * x * x;
    return 0.5f * x * (1.0f + tanhf(0.7978845608028654f * (x + 0.044715f * x3)));
}

__device__ __forceinline__ uint32_t smem_u32(const void* p) {
    uint32_t a;
    asm("{ .reg .u64 t; cvta.to.shared.u64 t, %1; cvt.u32.u64 %0, t; }" : "=r"(a) : "l"(p));
    return a;
}

__device__ __forceinline__ uint32_t pkh2(__half a, __half b) {
    return (uint32_t)__half_as_ushort(a) | ((uint32_t)__half_as_ushort(b) << 16);
}

__device__ __forceinline__ void cpasync16(uint32_t dst, const void* src) {
    asm volatile("cp.async.cg.shared.global [%0], [%1], 16;" :: "r"(dst), "l"(src));
}

__device__ __forceinline__ void ldm4(uint32_t* r, uint32_t a) {
    asm volatile("ldmatrix.sync.aligned.m8n8.x4.shared.b16 {%0,%1,%2,%3}, [%4];"
                 : "=r"(r[0]), "=r"(r[1]), "=r"(r[2]), "=r"(r[3]) : "r"(a));
}
__device__ __forceinline__ void mma16816(float* c, const uint32_t* a, const uint32_t* b) {
    asm volatile("mma.sync.aligned.m16n8k16.row.col.f32.f16.f16.f32 "
                 "{%0,%1,%2,%3}, {%4,%5,%6,%7}, {%8,%9}, {%0,%1,%2,%3};"
                 : "+f"(c[0]), "+f"(c[1]), "+f"(c[2]), "+f"(c[3])
                 : "r"(a[0]), "r"(a[1]), "r"(a[2]), "r"(a[3]), "r"(b[0]), "r"(b[1]));
}

// ---------------------------------------------------------------------------
// single fused weight convert: all four fp32 [K,N] -> fp16 transposed [N,K]
// sizes: qkv 442368 | proj 147456 | fc1 589824 | fc2 589824  (total 1769472)
// ---------------------------------------------------------------------------
__global__ void wconv_all(const float* __restrict__ w0, const float* __restrict__ w1,
                          const float* __restrict__ w2, const float* __restrict__ w3,
                          __half* __restrict__ o0, __half* __restrict__ o1,
                          __half* __restrict__ o2, __half* __restrict__ o3) {
    int idx = blockIdx.x * 256 + threadIdx.x;
    const float* w; __half* o; int N, K, off;
    if (idx < 442368)        { w = w0; o = o0; K = 384;  N = 1152; off = idx; }
    else if (idx < 589824)   { w = w1; o = o1; K = 384;  N = 384;  off = idx - 442368; }
    else if (idx < 1179648)  { w = w2; o = o2; K = 384;  N = 1536; off = idx - 589824; }
    else                     { w = w3; o = o3; K = 1536; N = 384;  off = idx - 1179648; }
    int k = off / N, n = off - k * N;
    o[(size_t)n * K + k] = __float2half_rn(w[off]);
}

// ---------------------------------------------------------------------------
// LayerNorm -> fp16. SHIFT gathers the shifted-window permutation.
// ---------------------------------------------------------------------------
template <bool SHIFT>
__global__ void ln_kernel(const float* __restrict__ x,
                          const float* __restrict__ gamma,
                          const float* __restrict__ beta,
                          __half* __restrict__ o) {
    int row = blockIdx.x;
    int src = SHIFT ? win2img(row) : row;
    const float* xp = x + (size_t)src * C_DIM;
    int tid = threadIdx.x;

    float v0 = xp[tid], v1 = xp[tid + 128], v2 = xp[tid + 256];
    float s  = v0 + v1 + v2;
    float sq = v0 * v0 + v1 * v1 + v2 * v2;
    #pragma unroll
    for (int off = 16; off > 0; off >>= 1) {
        s  += __shfl_down_sync(0xffffffffu, s,  off);
        sq += __shfl_down_sync(0xffffffffu, sq, off);
    }
    __shared__ float sa[4], sb[4];
    int wp = tid >> 5, ln = tid & 31;
    if (ln == 0) { sa[wp] = s; sb[wp] = sq; }
    __syncthreads();
    s  = sa[0] + sa[1] + sa[2] + sa[3];
    sq = sb[0] + sb[1] + sb[2] + sb[3];

    float mean = s * (1.0f / C_DIM);
    float var  = sq * (1.0f / C_DIM) - mean * mean;
    float inv  = rsqrtf(var + 1e-5f);

    size_t rb = (size_t)row * C_DIM;
    #pragma unroll
    for (int u = 0; u < 3; u++) {
        int c = tid + u * 128;
        float v = (u == 0 ? v0 : u == 1 ? v1 : v2);
        o[rb + c] = __float2half_rn((v - mean) * inv * gamma[c] + beta[c]);
    }
}

// ---------------------------------------------------------------------------
// fp16 HMMA GEMM: C = A[M,K] @ Bt[N,K]^T (+ bias + epilogue), fp32 accum.
// CTA tile 128x128, BK=64, 256 threads (8 warps 4x2, warp tile 32x64).
// cp.async 2-stage pipelined mainloop.
// EPI 0: bias -> fp16 out                          (qkv)
// EPI 1: bias + gelu -> fp16 out                   (fc1)
// EPI 2: bias + res[m] -> f32 out                  (fc2 + residual, final)
// EPI 3: bias + res[win2img(m)] -> f32 scattered   (proj + reverse + residual)
// ---------------------------------------------------------------------------
#define AS_STRIDE 72                      // halfs per row (64 + 8 pad) = 144 B
#define TILE_BYTES (128 * AS_STRIDE * 2)  // 18432 per tile
#define STAGE_BYTES (2 * TILE_BYTES)      // A + B
#define SMEM_BYTES (2 * STAGE_BYTES)      // 73728

template <int EPI>
__global__ __launch_bounds__(256)
void hgemm(const __half* __restrict__ A, const __half* __restrict__ B,
           const float* __restrict__ bias, const float* __restrict__ res,
           float* __restrict__ Cf, __half* __restrict__ Ch,
           int N, int K) {
    extern __shared__ __align__(16) char sm[];
    uint32_t sb = smem_u32(sm);

    int tid  = threadIdx.x;
    int lane = tid & 31;
    int wid  = tid >> 5;
    int warp_m = wid >> 1;
    int warp_n = wid & 1;
    int bm = blockIdx.y * 128, bn = blockIdx.x * 128;

    int lr = lane & 7;
    int aRow = warp_m * 32 + ((lane >> 3) & 1) * 8 + lr;
    int aCol = (lane >> 4) * 8;
    int bRow = warp_n * 64 + ((lane >> 4) & 1) * 8 + lr;
    int bCol = ((lane >> 3) & 1) * 8;

    float acc[2][8][4];
    #pragma unroll
    for (int i = 0; i < 2; i++)
        #pragma unroll
        for (int j = 0; j < 8; j++)
            #pragma unroll
            for (int e = 0; e < 4; e++) acc[i][j][e] = 0.0f;

    int ntile = K >> 6;
    int ldRow = tid >> 3;
    int ldSeg = tid & 7;
    #define LOAD_STAGE(t, s)                                                        \
    do {                                                                            \
        int k0_ = (t) << 6;                                                         \
        uint32_t dstA = sb + (s) * STAGE_BYTES + ldRow * 144 + ldSeg * 16;          \
        uint32_t dstB = dstA + TILE_BYTES;                                          \
        _Pragma("unroll")                                                           \
        for (int it = 0; it < 4; it++) {                                            \
            int row = ldRow + it * 32;                                              \
            cpasync16(dstA + it * 32 * 144,                                         \
                      (const uint4*)A + (((size_t)(bm + row) * K + k0_) >> 3) + ldSeg); \
            cpasync16(dstB + it * 32 * 144,                                         \
                      (const uint4*)B + (((size_t)(bn + row) * K + k0_) >> 3) + ldSeg); \
        }                                                                           \
        asm volatile("cp.async.commit_group;");                                     \
    } while (0)

    LOAD_STAGE(0, 0);

    for (int t = 0; t < ntile; t++) {
        if (t + 1 < ntile) {
            LOAD_STAGE(t + 1, (t + 1) & 1);
            asm volatile("cp.async.wait_group 1;");
        } else {
            asm volatile("cp.async.wait_group 0;");
        }
        __syncthreads();

        uint32_t offA = sb + (t & 1) * STAGE_BYTES;
        uint32_t offB = offA + TILE_BYTES;

        #pragma unroll
        for (int ks = 0; ks < 4; ks++) {
            uint32_t a[2][4], b[4][4];
            #pragma unroll
            for (int mt = 0; mt < 2; mt++)
                ldm4(a[mt], offA + (uint32_t)(((aRow + mt * 16) * AS_STRIDE) + ks * 16 + aCol) * 2);
            #pragma unroll
            for (int np = 0; np < 4; np++)
                ldm4(b[np], offB + (uint32_t)(((bRow + np * 16) * AS_STRIDE) + ks * 16 + bCol) * 2);
            #pragma unroll
            for (int mt = 0; mt < 2; mt++)
                #pragma unroll
                for (int np = 0; np < 4; np++) {
                    mma16816(acc[mt][np * 2 + 0], a[mt], &b[np][0]);
                    mma16816(acc[mt][np * 2 + 1], a[mt], &b[np][2]);
                }
        }
        __syncthreads();
    }

    #pragma unroll
    for (int mt = 0; mt < 2; mt++) {
        int row0 = bm + warp_m * 32 + mt * 16 + (lane >> 2);
        #pragma unroll
        for (int half = 0; half < 2; half++) {
            int row  = row0 + half * 8;
            int orow = (EPI == 3) ? win2img(row) : row;
            #pragma unroll
            for (int nt = 0; nt < 8; nt++) {
                int col = bn + warp_n * 64 + nt * 8 + (lane & 3) * 2;
                float c0 = acc[mt][nt][half * 2 + 0] + bias[col];
                float c1 = acc[mt][nt][half * 2 + 1] + bias[col + 1];
                if (EPI == 0 || EPI == 1) {
                    if (EPI == 1) { c0 = gelu_tanh(c0); c1 = gelu_tanh(c1); }
                    *(uint32_t*)&Ch[(size_t)row * N + col] =
                        pkh2(__float2half_rn(c0), __float2half_rn(c1));
                } else {
                    size_t o = (size_t)orow * N + col;
                    c0 += res[o]; c1 += res[o + 1];
                    *(float2*)&Cf[o] = make_float2(c0, c1);
                }
            }
        }
    }
}

// ---------------------------------------------------------------------------
// Tensor-core windowed attention. One block per (window, head), 4 warps.
// Warp owns 16 query rows: S = q k^T (HMMA, fp32 accum) -> scale+bias+mask
// -> register softmax -> P fragments repacked in registers -> O = P V (HMMA).
// qkv fp16 in, output fp16 at [token][h*32+d].
// ---------------------------------------------------------------------------
__global__ __launch_bounds__(128)
void attn_kernel(const __half* __restrict__ qkv,
                 const float* __restrict__ table,
                 __half* __restrict__ out) {
    __shared__ __half qs[64][40];
    __shared__ __half ks[64][40];
    __shared__ __half vt[32][72];     // V transposed: [d][m]
    __shared__ float  tbl[225];
    __shared__ int    cnt[64];

    int blk = blockIdx.x;
    int w = blk / NHEADS, h = blk - w * NHEADS;
    int tid = threadIdx.x, lane = tid & 31, wid = tid >> 5;

    const __half* base = qkv + (size_t)w * NTOK * QKV_N + h * HEADD;
    #pragma unroll
    for (int f = tid; f < 256; f += 128) {
        int n = f >> 2, seg = f & 3;
        const __half* rp = base + (size_t)n * QKV_N + seg * 8;
        *(uint4*)&qs[n][seg * 8] = *(const uint4*)rp;
        *(uint4*)&ks[n][seg * 8] = *(const uint4*)(rp + C_DIM);
        uint4 vv = *(const uint4*)(rp + 2 * C_DIM);
        __half hv[8]; *(uint4*)hv = vv;
        #pragma unroll
        for (int e = 0; e < 8; e++) vt[seg * 8 + e][n] = hv[e];
    }
    for (int i = tid; i < 225; i += 128) tbl[i] = table[i * NHEADS + h];
    if (tid < 64) {
        int wi = w & 15;
        int wh = wi >> 2, ww = wi & 3;
        int i = wh * 8 + (tid >> 3);
        int j = ww * 8 + (tid & 7);
        int ri = (i < 24) ? 0 : ((i < 28) ? 1 : 2);
        int rj = (j < 24) ? 0 : ((j < 28) ? 1 : 2);
        cnt[tid] = ri * 3 + rj;
    }
    __syncthreads();

    int lr = lane & 7;
    int aRow = wid * 16 + ((lane >> 3) & 1) * 8 + lr;
    int aCol = (lane >> 4) * 8;
    int bRow8 = ((lane >> 4) & 1) * 8 + lr;
    int bCol = ((lane >> 3) & 1) * 8;

    // S = q k^T : 64-col strip for this warp's 16 rows
    float s[8][4];
    #pragma unroll
    for (int j = 0; j < 8; j++)
        #pragma unroll
        for (int e = 0; e < 4; e++) s[j][e] = 0.0f;

    #pragma unroll
    for (int kk = 0; kk < 2; kk++) {
        uint32_t a[4];
        ldm4(a, smem_u32(&qs[aRow][kk * 16 + aCol]));
        #pragma unroll
        for (int np = 0; np < 4; np++) {
            uint32_t b[4];
            ldm4(b, smem_u32(&ks[np * 16 + bRow8][kk * 16 + bCol]));
            mma16816(s[np * 2 + 0], a, &b[0]);
            mma16816(s[np * 2 + 1], a, &b[2]);
        }
    }

    // scale + rel-pos bias + shift mask, register softmax (rows rA, rB)
    int rA = wid * 16 + (lane >> 2);
    int rB = rA + 8;
    int cA = cnt[rA], cB = cnt[rB];
    int r1A = rA >> 3, c1A = rA & 7;
    int r1B = rB >> 3, c1B = rB & 7;

    float mxA = -1e30f, mxB = -1e30f;
    #pragma unroll
    for (int j = 0; j < 8; j++)
        #pragma unroll
        for (int e = 0; e < 2; e++) {
            int m = j * 8 + (lane & 3) * 2 + e;
            int r2 = m >> 3, c2 = m & 7, cm = cnt[m];
            float bA = tbl[(r1A - r2 + 7) * 15 + (c1A - c2 + 7)] + (cA != cm ? -100.0f : 0.0f);
            float bB = tbl[(r1B - r2 + 7) * 15 + (c1B - c2 + 7)] + (cB != cm ? -100.0f : 0.0f);
            s[j][e]     = s[j][e]     * SCALE_ATTN + bA;
            s[j][e + 2] = s[j][e + 2] * SCALE_ATTN + bB;
            mxA = fmaxf(mxA, s[j][e]);
            mxB = fmaxf(mxB, s[j][e + 2]);
        }
    mxA = fmaxf(mxA, __shfl_xor_sync(0xffffffffu, mxA, 1));
    mxA = fmaxf(mxA, __shfl_xor_sync(0xffffffffu, mxA, 2));
    mxB = fmaxf(mxB, __shfl_xor_sync(0xffffffffu, mxB, 1));
    mxB = fmaxf(mxB, __shfl_xor_sync(0xffffffffu, mxB, 2));

    float smA = 0.0f, smB = 0.0f;
    #pragma unroll
    for (int j = 0; j < 8; j++)
        #pragma unroll
        for (int e = 0; e < 2; e++) {
            s[j][e]     = __expf(s[j][e]     - mxA);  smA += s[j][e];
            s[j][e + 2] = __expf(s[j][e + 2] - mxB);  smB += s[j][e + 2];
        }
    smA += __shfl_xor_sync(0xffffffffu, smA, 1);
    smA += __shfl_xor_sync(0xffffffffu, smA, 2);
    smB += __shfl_xor_sync(0xffffffffu, smB, 1);
    smB += __shfl_xor_sync(0xffffffffu, smB, 2);
    float invA = 1.0f / smA, invB = 1.0f / smB;

    // O = P V : P fragments built in registers (C-frag == A-frag layout)
    float o[4][4];
    #pragma unroll
    for (int j = 0; j < 4; j++)
        #pragma unroll
        for (int e = 0; e < 4; e++) o[j][e] = 0.0f;

    #pragma unroll
    for (int kk = 0; kk < 4; kk++) {
        uint32_t a[4];
        a[0] = pkh2(__float2half_rn(s[2 * kk][0] * invA),     __float2half_rn(s[2 * kk][1] * invA));
        a[1] = pkh2(__float2half_rn(s[2 * kk][2] * invB),     __float2half_rn(s[2 * kk][3] * invB));
        a[2] = pkh2(__float2half_rn(s[2 * kk + 1][0] * invA), __float2half_rn(s[2 * kk + 1][1] * invA));
        a[3] = pkh2(__float2half_rn(s[2 * kk + 1][2] * invB), __float2half_rn(s[2 * kk + 1][3] * invB));
        #pragma unroll
        for (int dp = 0; dp < 2; dp++) {
            uint32_t b[4];
            ldm4(b, smem_u32(&vt[dp * 16 + bRow8][kk * 16 + bCol]));
            mma16816(o[dp * 2 + 0], a, &b[0]);
            mma16816(o[dp * 2 + 1], a, &b[2]);
        }
    }

    __half* ob = out + (size_t)(w * NTOK) * C_DIM + h * HEADD;
    #pragma unroll
    for (int nt = 0; nt < 4; nt++) {
        int d = nt * 8 + (lane & 3) * 2;
        *(uint32_t*)&ob[(size_t)rA * C_DIM + d] =
            pkh2(__float2half_rn(o[nt][0]), __float2half_rn(o[nt][1]));
        *(uint32_t*)&ob[(size_t)rB * C_DIM + d] =
            pkh2(__float2half_rn(o[nt][2]), __float2half_rn(o[nt][3]));
    }
}

// ---------------------------------------------------------------------------
// launch
// ---------------------------------------------------------------------------
extern "C" void kernel_launch(void* const* d_in, const int* in_sizes, int n_in,
                              void* d_out, int out_size) {
    const float* x      = (const float*)d_in[0];
    const float* n1g    = (const float*)d_in[1];
    const float* n1b    = (const float*)d_in[2];
    const float* qkv_w  = (const float*)d_in[3];
    const float* qkv_b  = (const float*)d_in[4];
    const float* table  = (const float*)d_in[5];
    const float* proj_w = (const float*)d_in[6];
    const float* proj_b = (const float*)d_in[7];
    const float* n2g    = (const float*)d_in[8];
    const float* n2b    = (const float*)d_in[9];
    const float* fc1_w  = (const float*)d_in[10];
    const float* fc1_b  = (const float*)d_in[11];
    const float* fc2_w  = (const float*)d_in[12];
    const float* fc2_b  = (const float*)d_in[13];
    float* out = (float*)d_out;

    static __half *xw, *qkvh, *at, *n2, *hbuf, *wqkv, *wpr, *wf1, *wf2;
    static float *x1;
    static bool init = false;
    if (!init) {
        init = true;
        cudaGetSymbolAddress((void**)&xw,   g_xw);
        cudaGetSymbolAddress((void**)&qkvh, g_qkv);
        cudaGetSymbolAddress((void**)&at,   g_at);
        cudaGetSymbolAddress((void**)&n2,   g_n2);
        cudaGetSymbolAddress((void**)&hbuf, g_h);
        cudaGetSymbolAddress((void**)&wqkv, g_wqkv);
        cudaGetSymbolAddress((void**)&wpr,  g_wpr);
        cudaGetSymbolAddress((void**)&wf1,  g_wf1);
        cudaGetSymbolAddress((void**)&wf2,  g_wf2);
        cudaGetSymbolAddress((void**)&x1,   g_x1);
        cudaFuncSetAttribute(hgemm<0>, cudaFuncAttributeMaxDynamicSharedMemorySize, SMEM_BYTES);
        cudaFuncSetAttribute(hgemm<1>, cudaFuncAttributeMaxDynamicSharedMemorySize, SMEM_BYTES);
        cudaFuncSetAttribute(hgemm<2>, cudaFuncAttributeMaxDynamicSharedMemorySize, SMEM_BYTES);
        cudaFuncSetAttribute(hgemm<3>, cudaFuncAttributeMaxDynamicSharedMemorySize, SMEM_BYTES);
    }

    // 0) fused weight convert + transpose (fp16)
    wconv_all<<<6912, 256>>>(qkv_w, proj_w, fc1_w, fc2_w, wqkv, wpr, wf1, wf2);

    // 1) LN1 + shift + window partition -> fp16
    ln_kernel<true><<<M_TOK, 128>>>(x, n1g, n1b, xw);

    // 2) QKV GEMM -> fp16
    {
        dim3 grid(QKV_N / 128, M_TOK / 128);
        hgemm<0><<<grid, 256, SMEM_BYTES>>>(xw, wqkv, qkv_b, nullptr,
                                            nullptr, qkvh, QKV_N, C_DIM);
    }

    // 3) tensor-core windowed attention -> fp16
    attn_kernel<<<512 * NHEADS, 128>>>(qkvh, table, at);

    // 4) proj + reverse/unshift scatter + residual -> x1 (f32, image layout)
    {
        dim3 grid(C_DIM / 128, M_TOK / 128);
        hgemm<3><<<grid, 256, SMEM_BYTES>>>(at, wpr, proj_b, x,
                                            x1, nullptr, C_DIM, C_DIM);
    }

    // 5) LN2 -> fp16
    ln_kernel<false><<<M_TOK, 128>>>(x1, n2g, n2b, n2);

    // 6) FC1 + GELU -> fp16
    {
        dim3 grid(HIDDEN / 128, M_TOK / 128);
        hgemm<1><<<grid, 256, SMEM_BYTES>>>(n2, wf1, fc1_b, nullptr,
                                            nullptr, hbuf, HIDDEN, C_DIM);
    }

    // 7) FC2 + residual -> out (f32)
    {
        dim3 grid(C_DIM / 128, M_TOK / 128);
        hgemm<2><<<grid, 256, SMEM_BYTES>>>(hbuf, wf2, fc2_b, x1,
                                            out, nullptr, C_DIM, HIDDEN);
    }
}